// round 6
// baseline (speedup 1.0000x reference)
#include <cuda_runtime.h>
#include <math.h>

#define D_MODEL 1024
#define N_RES   2048
#define BATCH   32
#define TWO_D   2048
#define TILE_D  8
#define KSPLIT  4
#define NSPLIT  4
#define DSPLIT  4
#define DCHUNK  (D_MODEL / DSPLIT)   // 256

// ---- scratch (device globals; no allocation allowed) ----
__device__ __align__(16) float g_xcombT[TWO_D * BATCH];                  // [k][b]
__device__ __align__(16) float g_xc_part[KSPLIT * D_MODEL * BATCH];      // [s][d][b]
__device__ __align__(16) float g_xcT  [D_MODEL * BATCH];                 // [d][b]
__device__ __align__(16) float g_rw   [N_RES * D_MODEL];                 // 1/(1+|W|)
__device__ __align__(16) float g_cos_part[DSPLIT * N_RES * BATCH];       // [s][n][b]
__device__ __align__(16) float g_sin_part[DSPLIT * N_RES * BATCH];
__device__ __align__(16) float g_cosT [N_RES * BATCH];                   // rotated sums [n][b]
__device__ __align__(16) float g_sinT [N_RES * BATCH];
__device__ __align__(16) float g_out_part[NSPLIT * 2 * D_MODEL * BATCH]; // [s][row][b]

// ---------------------------------------------------------------------------
// K0 (fused): blocks [0,64) transpose x -> xcombT via smem tiles;
//             blocks [64, 576) stream W -> 1/(1+|W|).
// ---------------------------------------------------------------------------
__global__ void __launch_bounds__(256)
prep_kernel(const float* __restrict__ xr,
            const float* __restrict__ xi,
            const float* __restrict__ W) {
    if (blockIdx.x < 64) {
        __shared__ float tile[32][33];
        const int k0   = blockIdx.x * 32;
        const int w    = threadIdx.x >> 5;
        const int lane = threadIdx.x & 31;
        #pragma unroll
        for (int bb = w; bb < 32; bb += 8) {
            int k = k0 + lane;
            float v = (k < D_MODEL) ? xr[bb * D_MODEL + k]
                                    : xi[bb * D_MODEL + (k - D_MODEL)];
            tile[lane][bb] = v;                 // [k_local][b]
        }
        __syncthreads();
        #pragma unroll
        for (int kk = w; kk < 32; kk += 8)
            g_xcombT[(k0 + kk) * BATCH + lane] = tile[kk][lane];
    } else {
        int i = (blockIdx.x - 64) * 256 + threadIdx.x;
        int stride = (gridDim.x - 64) * 256;
        const float4* W4 = (const float4*)W;
        float4* rw4 = (float4*)g_rw;
        const int n4 = N_RES * D_MODEL / 4;
        for (int idx = i; idx < n4; idx += stride) {
            float4 w = W4[idx];
            float4 r;
            r.x = 1.0f / (1.0f + fabsf(w.x));
            r.y = 1.0f / (1.0f + fabsf(w.y));
            r.z = 1.0f / (1.0f + fabsf(w.z));
            r.w = 1.0f / (1.0f + fabsf(w.w));
            rw4[idx] = r;
        }
    }
}

// ---------------------------------------------------------------------------
// K1: input projection, split-K, weights staged in smem (coalesced).
// ---------------------------------------------------------------------------
__global__ void __launch_bounds__(256)
proj_kernel(const float* __restrict__ ipw) {
    __shared__ float s_w[TILE_D * 512];          // 16 KB
    __shared__ float red[8][TILE_D][32];         // 8 KB
    const int dt    = blockIdx.x * TILE_D;
    const int split = blockIdx.y;
    const int kbase = split * 512;
    const int w     = threadIdx.x >> 5;
    const int lane  = threadIdx.x & 31;

    #pragma unroll
    for (int p = 0; p < 4; p++) {
        int idx = p * 256 + threadIdx.x;
        int r = idx >> 7;
        int c = (idx & 127) * 4;
        *(float4*)(s_w + r * 512 + c) =
            *(const float4*)(ipw + (size_t)(dt + r) * TWO_D + kbase + c);
    }
    __syncthreads();

    float acc[TILE_D];
    #pragma unroll
    for (int i = 0; i < TILE_D; i++) acc[i] = 0.f;

    const int k0 = w * 64;
    for (int k = k0; k < k0 + 64; k += 4) {
        int gk = kbase + k;
        float s0 = g_xcombT[(gk + 0) * BATCH + lane];
        float s1 = g_xcombT[(gk + 1) * BATCH + lane];
        float s2 = g_xcombT[(gk + 2) * BATCH + lane];
        float s3 = g_xcombT[(gk + 3) * BATCH + lane];
        #pragma unroll
        for (int i = 0; i < TILE_D; i++) {
            float4 w4 = *(const float4*)(s_w + i * 512 + k);
            acc[i] = fmaf(s3, w4.w, fmaf(s2, w4.z, fmaf(s1, w4.y, fmaf(s0, w4.x, acc[i]))));
        }
    }
    #pragma unroll
    for (int i = 0; i < TILE_D; i++) red[w][i][lane] = acc[i];
    __syncthreads();

    const int td = threadIdx.x >> 5;
    float s = 0.f;
    #pragma unroll
    for (int ww = 0; ww < 8; ww++) s += red[ww][td][lane];
    g_xc_part[(split * D_MODEL + dt + td) * BATCH + lane] = s;
}

// K1b: combine split-K partials + bias
__global__ void combine_xc_kernel(const float* __restrict__ ipb) {
    int idx = blockIdx.x * blockDim.x + threadIdx.x;
    if (idx >= D_MODEL * BATCH) return;
    int d = idx >> 5;
    float s = 0.f;
    #pragma unroll
    for (int sp = 0; sp < KSPLIT; sp++)
        s += g_xc_part[sp * D_MODEL * BATCH + idx];
    g_xcT[idx] = s + __ldg(ipb + d);
}

// ---------------------------------------------------------------------------
// K2: resonance, 4-way d-split, NO smem staging (warp-uniform LDG, L1 hits).
// warp w owns n = n0+w, lane = b.  core = xc*rw + B (t applied in combine).
// ---------------------------------------------------------------------------
__global__ void __launch_bounds__(256, 6)
resonance_kernel(const float* __restrict__ Bmat) {
    const int n    = blockIdx.x * 8 + (threadIdx.x >> 5);
    const int c0   = blockIdx.y * DCHUNK;
    const int lane = threadIdx.x & 31;

    const float4* rwp = (const float4*)(g_rw + (size_t)n * D_MODEL + c0);
    const float4* bp  = (const float4*)(Bmat + (size_t)n * D_MODEL + c0);
    const float*  xcp = g_xcT + (size_t)c0 * BATCH + lane;

    float ca0 = 0.f, ca1 = 0.f, sa0 = 0.f, sa1 = 0.f;

    #pragma unroll 4
    for (int i = 0; i < DCHUNK / 4; i++) {
        float4 rw4 = __ldg(rwp + i);
        float4 b4  = __ldg(bp  + i);

        float xc0 = xcp[(i * 4 + 0) * BATCH];
        float xc1 = xcp[(i * 4 + 1) * BATCH];
        float xc2 = xcp[(i * 4 + 2) * BATCH];
        float xc3 = xcp[(i * 4 + 3) * BATCH];

        float th0 = fmaf(xc0, rw4.x, b4.x);
        float th1 = fmaf(xc1, rw4.y, b4.y);
        float th2 = fmaf(xc2, rw4.z, b4.z);
        float th3 = fmaf(xc3, rw4.w, b4.w);

        sa0 += __sinf(th0);  ca0 += __cosf(th0);
        sa1 += __sinf(th1);  ca1 += __cosf(th1);
        sa0 += __sinf(th2);  ca0 += __cosf(th2);
        sa1 += __sinf(th3);  ca1 += __cosf(th3);
    }
    g_cos_part[(blockIdx.y * N_RES + n) * BATCH + lane] = ca0 + ca1;
    g_sin_part[(blockIdx.y * N_RES + n) * BATCH + lane] = sa0 + sa1;
}

// K2b: combine d-split partials and rotate by t[b]
__global__ void combine_res_kernel(const float* __restrict__ t) {
    int idx = blockIdx.x * blockDim.x + threadIdx.x;   // N*B
    if (idx >= N_RES * BATCH) return;
    int b = idx & 31;
    float C = 0.f, S = 0.f;
    #pragma unroll
    for (int sp = 0; sp < DSPLIT; sp++) {
        C += g_cos_part[sp * N_RES * BATCH + idx];
        S += g_sin_part[sp * N_RES * BATCH + idx];
    }
    float st, ct;
    __sincosf(__ldg(t + b), &st, &ct);
    g_cosT[idx] = fmaf(C, ct, -S * st);
    g_sinT[idx] = fmaf(S, ct,  C * st);
}

// ---------------------------------------------------------------------------
// K3: output projection, split-N, weights staged in smem (coalesced).
// ---------------------------------------------------------------------------
__global__ void __launch_bounds__(256)
outproj_kernel(const float* __restrict__ wr,
               const float* __restrict__ wi) {
    __shared__ float s_w[TILE_D * 512];          // 16 KB
    __shared__ float red[8][TILE_D][32];
    const int  dt      = blockIdx.x * TILE_D;
    const int  split   = blockIdx.y;
    const bool is_imag = blockIdx.z != 0;
    const int  nbase   = split * 512;
    const int  w       = threadIdx.x >> 5;
    const int  lane    = threadIdx.x & 31;

    const float* wbase = is_imag ? wi : wr;
    const float* src   = is_imag ? g_sinT : g_cosT;

    #pragma unroll
    for (int p = 0; p < 4; p++) {
        int idx = p * 256 + threadIdx.x;
        int r = idx >> 7;
        int c = (idx & 127) * 4;
        *(float4*)(s_w + r * 512 + c) =
            *(const float4*)(wbase + (size_t)(dt + r) * N_RES + nbase + c);
    }
    __syncthreads();

    float acc[TILE_D];
    #pragma unroll
    for (int i = 0; i < TILE_D; i++) acc[i] = 0.f;

    const int n0 = w * 64;
    for (int n = n0; n < n0 + 64; n += 4) {
        int gn = nbase + n;
        float s0 = src[(gn + 0) * BATCH + lane];
        float s1 = src[(gn + 1) * BATCH + lane];
        float s2 = src[(gn + 2) * BATCH + lane];
        float s3 = src[(gn + 3) * BATCH + lane];
        #pragma unroll
        for (int i = 0; i < TILE_D; i++) {
            float4 w4 = *(const float4*)(s_w + i * 512 + n);
            acc[i] = fmaf(s3, w4.w, fmaf(s2, w4.z, fmaf(s1, w4.y, fmaf(s0, w4.x, acc[i]))));
        }
    }
    #pragma unroll
    for (int i = 0; i < TILE_D; i++) red[w][i][lane] = acc[i];
    __syncthreads();

    const int td = threadIdx.x >> 5;
    float s = 0.f;
    #pragma unroll
    for (int ww = 0; ww < 8; ww++) s += red[ww][td][lane];
    const int row = (is_imag ? D_MODEL : 0) + dt + td;
    g_out_part[(split * 2 * D_MODEL + row) * BATCH + lane] = s;
}

// K3b: combine split-N partials, silu, coalesced transpose store (32x32 tiles)
__global__ void __launch_bounds__(256)
combine_out_kernel(float* __restrict__ out) {
    __shared__ float tile[32][33];
    const int row0 = blockIdx.x * 32;
    const int w    = threadIdx.x >> 5;
    const int lane = threadIdx.x & 31;

    #pragma unroll
    for (int rr = w; rr < 32; rr += 8) {
        int idx = (row0 + rr) * BATCH + lane;
        float s = 0.f;
        #pragma unroll
        for (int sp = 0; sp < NSPLIT; sp++)
            s += g_out_part[sp * 2 * D_MODEL * BATCH + idx];
        tile[rr][lane] = s / (1.0f + __expf(-s));
    }
    __syncthreads();

    // rows in this block are all on one side (32 | D_MODEL)
    const int is_imag = row0 >= D_MODEL;
    #pragma unroll
    for (int bb = w; bb < 32; bb += 8) {
        int d = (row0 + lane) & (D_MODEL - 1);
        out[(is_imag ? BATCH * D_MODEL : 0) + bb * D_MODEL + d] = tile[lane][bb];
    }
}

// ---------------------------------------------------------------------------
extern "C" void kernel_launch(void* const* d_in, const int* in_sizes, int n_in,
                              void* d_out, int out_size) {
    const float* x_real = (const float*)d_in[0];
    const float* x_imag = (const float*)d_in[1];
    const float* t      = (const float*)d_in[2];
    const float* ipw    = (const float*)d_in[3];
    const float* ipb    = (const float*)d_in[4];
    const float* W      = (const float*)d_in[5];
    const float* Bmat   = (const float*)d_in[6];
    const float* orw    = (const float*)d_in[7];
    const float* oiw    = (const float*)d_in[8];
    float* out = (float*)d_out;

    prep_kernel<<<576, 256>>>(x_real, x_imag, W);
    proj_kernel<<<dim3(D_MODEL / TILE_D, KSPLIT), 256>>>(ipw);
    combine_xc_kernel<<<(D_MODEL * BATCH + 255) / 256, 256>>>(ipb);
    resonance_kernel<<<dim3(N_RES / 8, DSPLIT), 256>>>(Bmat);
    combine_res_kernel<<<(N_RES * BATCH + 255) / 256, 256>>>(t);
    outproj_kernel<<<dim3(D_MODEL / TILE_D, NSPLIT, 2), 256>>>(orw, oiw);
    combine_out_kernel<<<2 * D_MODEL / 32, 256>>>(out);
}

// round 7
// speedup vs baseline: 1.1203x; 1.1203x over previous
#include <cuda_runtime.h>
#include <math.h>

#define D_MODEL 1024
#define N_RES   2048
#define BATCH   32
#define TWO_D   2048
#define TILE_D  8
#define KSPLIT  4
#define NSPLIT  4
#define DSPLIT  8
#define CHUNK   128

// ---- scratch (device globals; no allocation allowed) ----
__device__ __align__(16) float g_xcombT[TWO_D * BATCH];                  // [k][b]
__device__ __align__(16) float g_xc_part[KSPLIT * D_MODEL * BATCH];      // [s][d][b]
__device__ __align__(16) float g_xcT  [D_MODEL * BATCH];                 // [d][b]
__device__ __align__(16) float g_rw   [N_RES * D_MODEL];                 // 1/(1+|W|)
__device__ __align__(16) float g_cos_part[DSPLIT * N_RES * BATCH];       // [s][n][b]
__device__ __align__(16) float g_sin_part[DSPLIT * N_RES * BATCH];
__device__ __align__(16) float g_cosT [N_RES * BATCH];                   // rotated sums [n][b]
__device__ __align__(16) float g_sinT [N_RES * BATCH];
__device__ __align__(16) float g_out_part[NSPLIT * 2 * D_MODEL * BATCH]; // [s][row][b]

// ---------------------------------------------------------------------------
// K0 (fused): blocks [0,64) transpose x -> xcombT via smem tiles;
//             blocks [64, 576) stream W -> 1/(1+|W|).
// ---------------------------------------------------------------------------
__global__ void __launch_bounds__(256)
prep_kernel(const float* __restrict__ xr,
            const float* __restrict__ xi,
            const float* __restrict__ W) {
    if (blockIdx.x < 64) {
        __shared__ float tile[32][33];
        const int k0   = blockIdx.x * 32;
        const int w    = threadIdx.x >> 5;
        const int lane = threadIdx.x & 31;
        #pragma unroll
        for (int bb = w; bb < 32; bb += 8) {
            int k = k0 + lane;
            float v = (k < D_MODEL) ? xr[bb * D_MODEL + k]
                                    : xi[bb * D_MODEL + (k - D_MODEL)];
            tile[lane][bb] = v;                 // [k_local][b]
        }
        __syncthreads();
        #pragma unroll
        for (int kk = w; kk < 32; kk += 8)
            g_xcombT[(k0 + kk) * BATCH + lane] = tile[kk][lane];
    } else {
        int i = (blockIdx.x - 64) * 256 + threadIdx.x;
        int stride = (gridDim.x - 64) * 256;
        const float4* W4 = (const float4*)W;
        float4* rw4 = (float4*)g_rw;
        const int n4 = N_RES * D_MODEL / 4;
        for (int idx = i; idx < n4; idx += stride) {
            float4 w = W4[idx];
            float4 r;
            r.x = 1.0f / (1.0f + fabsf(w.x));
            r.y = 1.0f / (1.0f + fabsf(w.y));
            r.z = 1.0f / (1.0f + fabsf(w.z));
            r.w = 1.0f / (1.0f + fabsf(w.w));
            rw4[idx] = r;
        }
    }
}

// ---------------------------------------------------------------------------
// K1: input projection, split-K, weights staged in smem (coalesced).
// ---------------------------------------------------------------------------
__global__ void __launch_bounds__(256)
proj_kernel(const float* __restrict__ ipw) {
    __shared__ float s_w[TILE_D * 512];          // 16 KB
    __shared__ float red[8][TILE_D][32];         // 8 KB
    const int dt    = blockIdx.x * TILE_D;
    const int split = blockIdx.y;
    const int kbase = split * 512;
    const int w     = threadIdx.x >> 5;
    const int lane  = threadIdx.x & 31;

    #pragma unroll
    for (int p = 0; p < 4; p++) {
        int idx = p * 256 + threadIdx.x;
        int r = idx >> 7;
        int c = (idx & 127) * 4;
        *(float4*)(s_w + r * 512 + c) =
            *(const float4*)(ipw + (size_t)(dt + r) * TWO_D + kbase + c);
    }
    __syncthreads();

    float acc[TILE_D];
    #pragma unroll
    for (int i = 0; i < TILE_D; i++) acc[i] = 0.f;

    const int k0 = w * 64;
    for (int k = k0; k < k0 + 64; k += 4) {
        int gk = kbase + k;
        float s0 = g_xcombT[(gk + 0) * BATCH + lane];
        float s1 = g_xcombT[(gk + 1) * BATCH + lane];
        float s2 = g_xcombT[(gk + 2) * BATCH + lane];
        float s3 = g_xcombT[(gk + 3) * BATCH + lane];
        #pragma unroll
        for (int i = 0; i < TILE_D; i++) {
            float4 w4 = *(const float4*)(s_w + i * 512 + k);
            acc[i] = fmaf(s3, w4.w, fmaf(s2, w4.z, fmaf(s1, w4.y, fmaf(s0, w4.x, acc[i]))));
        }
    }
    #pragma unroll
    for (int i = 0; i < TILE_D; i++) red[w][i][lane] = acc[i];
    __syncthreads();

    const int td = threadIdx.x >> 5;
    float s = 0.f;
    #pragma unroll
    for (int ww = 0; ww < 8; ww++) s += red[ww][td][lane];
    g_xc_part[(split * D_MODEL + dt + td) * BATCH + lane] = s;
}

// K1b: combine split-K partials + bias
__global__ void combine_xc_kernel(const float* __restrict__ ipb) {
    int idx = blockIdx.x * blockDim.x + threadIdx.x;
    if (idx >= D_MODEL * BATCH) return;
    int d = idx >> 5;
    float s = 0.f;
    #pragma unroll
    for (int sp = 0; sp < KSPLIT; sp++)
        s += g_xc_part[sp * D_MODEL * BATCH + idx];
    g_xcT[idx] = s + __ldg(ipb + d);
}

// ---------------------------------------------------------------------------
// K2: resonance, 8-way d-split; one 128-d chunk per block.
// ALL hot-loop operands staged in smem (rw, B, xc). warp w owns n, lane = b.
// ---------------------------------------------------------------------------
__global__ void __launch_bounds__(256, 6)
resonance_kernel(const float* __restrict__ Bmat) {
    __shared__ float s_rw[8 * CHUNK];            // 4 KB
    __shared__ float s_B [8 * CHUNK];            // 4 KB
    __shared__ float s_xc[CHUNK * BATCH];        // 16 KB

    const int n0    = blockIdx.x * 8;
    const int split = blockIdx.y;
    const int c0    = split * CHUNK;
    const int w     = threadIdx.x >> 5;
    const int lane  = threadIdx.x & 31;

    {
        const int off = lane * 4;
        *(float4*)(s_rw + w * CHUNK + off) =
            *(const float4*)(g_rw + (size_t)(n0 + w) * D_MODEL + c0 + off);
        *(float4*)(s_B + w * CHUNK + off) =
            *(const float4*)(Bmat + (size_t)(n0 + w) * D_MODEL + c0 + off);
        // stage xc chunk: 4096 floats = 1024 float4, 4 per thread
        const float4* src = (const float4*)(g_xcT + (size_t)c0 * BATCH);
        float4* dst = (float4*)s_xc;
        #pragma unroll
        for (int p = 0; p < 4; p++)
            dst[p * 256 + threadIdx.x] = src[p * 256 + threadIdx.x];
    }
    __syncthreads();

    float ca0 = 0.f, ca1 = 0.f, sa0 = 0.f, sa1 = 0.f;

    #pragma unroll 4
    for (int d = 0; d < CHUNK; d += 4) {
        float4 rw4 = *(const float4*)(s_rw + w * CHUNK + d);
        float4 b4  = *(const float4*)(s_B  + w * CHUNK + d);

        float xc0 = s_xc[(d + 0) * BATCH + lane];
        float xc1 = s_xc[(d + 1) * BATCH + lane];
        float xc2 = s_xc[(d + 2) * BATCH + lane];
        float xc3 = s_xc[(d + 3) * BATCH + lane];

        float th0 = fmaf(xc0, rw4.x, b4.x);
        float th1 = fmaf(xc1, rw4.y, b4.y);
        float th2 = fmaf(xc2, rw4.z, b4.z);
        float th3 = fmaf(xc3, rw4.w, b4.w);

        sa0 += __sinf(th0);  ca0 += __cosf(th0);
        sa1 += __sinf(th1);  ca1 += __cosf(th1);
        sa0 += __sinf(th2);  ca0 += __cosf(th2);
        sa1 += __sinf(th3);  ca1 += __cosf(th3);
    }
    g_cos_part[(split * N_RES + n0 + w) * BATCH + lane] = ca0 + ca1;
    g_sin_part[(split * N_RES + n0 + w) * BATCH + lane] = sa0 + sa1;
}

// K2b: combine d-split partials and rotate by t[b]
__global__ void combine_res_kernel(const float* __restrict__ t) {
    int idx = blockIdx.x * blockDim.x + threadIdx.x;   // N*B
    if (idx >= N_RES * BATCH) return;
    int b = idx & 31;
    float C = 0.f, S = 0.f;
    #pragma unroll
    for (int sp = 0; sp < DSPLIT; sp++) {
        C += g_cos_part[sp * N_RES * BATCH + idx];
        S += g_sin_part[sp * N_RES * BATCH + idx];
    }
    float st, ct;
    __sincosf(__ldg(t + b), &st, &ct);
    g_cosT[idx] = fmaf(C, ct, -S * st);
    g_sinT[idx] = fmaf(S, ct,  C * st);
}

// ---------------------------------------------------------------------------
// K3: output projection, split-N, weights staged in smem (coalesced).
// ---------------------------------------------------------------------------
__global__ void __launch_bounds__(256)
outproj_kernel(const float* __restrict__ wr,
               const float* __restrict__ wi) {
    __shared__ float s_w[TILE_D * 512];          // 16 KB
    __shared__ float red[8][TILE_D][32];
    const int  dt      = blockIdx.x * TILE_D;
    const int  split   = blockIdx.y;
    const bool is_imag = blockIdx.z != 0;
    const int  nbase   = split * 512;
    const int  w       = threadIdx.x >> 5;
    const int  lane    = threadIdx.x & 31;

    const float* wbase = is_imag ? wi : wr;
    const float* src   = is_imag ? g_sinT : g_cosT;

    #pragma unroll
    for (int p = 0; p < 4; p++) {
        int idx = p * 256 + threadIdx.x;
        int r = idx >> 7;
        int c = (idx & 127) * 4;
        *(float4*)(s_w + r * 512 + c) =
            *(const float4*)(wbase + (size_t)(dt + r) * N_RES + nbase + c);
    }
    __syncthreads();

    float acc[TILE_D];
    #pragma unroll
    for (int i = 0; i < TILE_D; i++) acc[i] = 0.f;

    const int n0 = w * 64;
    for (int n = n0; n < n0 + 64; n += 4) {
        int gn = nbase + n;
        float s0 = src[(gn + 0) * BATCH + lane];
        float s1 = src[(gn + 1) * BATCH + lane];
        float s2 = src[(gn + 2) * BATCH + lane];
        float s3 = src[(gn + 3) * BATCH + lane];
        #pragma unroll
        for (int i = 0; i < TILE_D; i++) {
            float4 w4 = *(const float4*)(s_w + i * 512 + n);
            acc[i] = fmaf(s3, w4.w, fmaf(s2, w4.z, fmaf(s1, w4.y, fmaf(s0, w4.x, acc[i]))));
        }
    }
    #pragma unroll
    for (int i = 0; i < TILE_D; i++) red[w][i][lane] = acc[i];
    __syncthreads();

    const int td = threadIdx.x >> 5;
    float s = 0.f;
    #pragma unroll
    for (int ww = 0; ww < 8; ww++) s += red[ww][td][lane];
    const int row = (is_imag ? D_MODEL : 0) + dt + td;
    g_out_part[(split * 2 * D_MODEL + row) * BATCH + lane] = s;
}

// K3b: combine split-N partials, silu, coalesced transpose store (32x32 tiles)
__global__ void __launch_bounds__(256)
combine_out_kernel(float* __restrict__ out) {
    __shared__ float tile[32][33];
    const int row0 = blockIdx.x * 32;
    const int w    = threadIdx.x >> 5;
    const int lane = threadIdx.x & 31;

    #pragma unroll
    for (int rr = w; rr < 32; rr += 8) {
        int idx = (row0 + rr) * BATCH + lane;
        float s = 0.f;
        #pragma unroll
        for (int sp = 0; sp < NSPLIT; sp++)
            s += g_out_part[sp * 2 * D_MODEL * BATCH + idx];
        tile[rr][lane] = s / (1.0f + __expf(-s));
    }
    __syncthreads();

    const int is_imag = row0 >= D_MODEL;
    #pragma unroll
    for (int bb = w; bb < 32; bb += 8) {
        int d = (row0 + lane) & (D_MODEL - 1);
        out[(is_imag ? BATCH * D_MODEL : 0) + bb * D_MODEL + d] = tile[lane][bb];
    }
}

// ---------------------------------------------------------------------------
extern "C" void kernel_launch(void* const* d_in, const int* in_sizes, int n_in,
                              void* d_out, int out_size) {
    const float* x_real = (const float*)d_in[0];
    const float* x_imag = (const float*)d_in[1];
    const float* t      = (const float*)d_in[2];
    const float* ipw    = (const float*)d_in[3];
    const float* ipb    = (const float*)d_in[4];
    const float* W      = (const float*)d_in[5];
    const float* Bmat   = (const float*)d_in[6];
    const float* orw    = (const float*)d_in[7];
    const float* oiw    = (const float*)d_in[8];
    float* out = (float*)d_out;

    prep_kernel<<<576, 256>>>(x_real, x_imag, W);
    proj_kernel<<<dim3(D_MODEL / TILE_D, KSPLIT), 256>>>(ipw);
    combine_xc_kernel<<<(D_MODEL * BATCH + 255) / 256, 256>>>(ipb);
    resonance_kernel<<<dim3(N_RES / 8, DSPLIT), 256>>>(Bmat);
    combine_res_kernel<<<(N_RES * BATCH + 255) / 256, 256>>>(t);
    outproj_kernel<<<dim3(D_MODEL / TILE_D, NSPLIT, 2), 256>>>(orw, oiw);
    combine_out_kernel<<<2 * D_MODEL / 32, 256>>>(out);
}